// round 5
// baseline (speedup 1.0000x reference)
#include <cuda_runtime.h>
#include <cuda_bf16.h>
#include <cstdint>

// EAM potential, symmetry-halved tiled kernel (NT==2 fast path) with fused
// last-block finalize. Fallback: R2 warp-per-row kernel for other shapes.
//
// Inputs (metadata order):
//   0 distances [B,N,N] f32   1 A[NPT]   2 p[NPT]   3 xi[NPT]   4 q[NPT]
//   5 r0[NPT]  6 cut_a[NPT]   7 cut_b[NPT]  8 emb_scale[NT]  9 offset[NT]
//  10 types [B,N] i32        11 pair_types (UNUSED, recomputed from types)
// Output: [B,2] f32 = {energy, energy/n_atoms}

#define MAX_B   64
#define MAX_BN  65536
#define TS      128     // tile size (cols)
#define HROWS   64      // rows per block (half tile)
#define FIX_SCALE 268435456.0   // 2^28 fixed point (exact, order-independent)

// zero at module load; finalize/last-block resets for every graph replay
__device__ unsigned long long g_phi[MAX_BN];
__device__ unsigned long long g_rho[MAX_BN];
__device__ unsigned int       g_ticket;
// fallback-path scratch
__device__ long long g_energy_fix[MAX_B];
__device__ int       g_count[MAX_B];

__device__ __forceinline__ float ex2_approx(float x) {
    float y; asm("ex2.approx.f32 %0, %1;" : "=f"(y) : "f"(x)); return y;
}
__device__ __forceinline__ float fma_sat(float a, float b, float c) {
    float y; asm("fma.rn.sat.f32 %0, %1, %2, %3;" : "=f"(y) : "f"(a), "f"(b), "f"(c)); return y;
}
__device__ __forceinline__ unsigned long long f2fix(float v) {
    return (unsigned long long)(long long)__float2ll_rn(v * (float)FIX_SCALE);
}
__device__ __forceinline__ int pair_type(int ti, int tj, int NT) {
    int tmin = min(ti, tj), tmax = max(ti, tj);
    return tmin * NT - (tmin * (tmin - 1)) / 2 + (tmax - tmin);
}

// ───────────────────────── fast path: symmetric tiles ─────────────────────────

__global__ void __launch_bounds__(256)
eam_tile_kernel(const float* __restrict__ dist,      // [B,N,N]
                const int*   __restrict__ types,     // [B,N]
                const float* __restrict__ A,  const float* __restrict__ p,
                const float* __restrict__ xi, const float* __restrict__ q,
                const float* __restrict__ r0, const float* __restrict__ cut_a,
                const float* __restrict__ cut_b,
                const float* __restrict__ emb_scale,
                const float* __restrict__ offset,
                int N, int B, int ntile, int upb,    // upb = ntile*(ntile+1)/2
                float* __restrict__ out)
{
    // ── decode block → (batch, tile ti<=tj, half) ──
    const int perB = upb * 2;
    const int b    = blockIdx.x / perB;
    const int rem  = blockIdx.x % perB;
    const int u    = rem >> 1;
    const int half = rem & 1;
    int ti = 0, rr_ = u;
    while (rr_ >= ntile - ti) { rr_ -= ntile - ti; ti++; }
    const int tj   = ti + rr_;
    const bool diag = (ti == tj);

    // ── per-pair-type constants (NT==2 → pt = t_i + t_j ∈ {0,1,2}) ──
    const float L2E = 1.4426950408889634f;
    float pU1[3], pC1[3], pU2[3], pC2[3], pIB[3], pNA[3];
    #pragma unroll
    for (int k = 0; k < 3; k++) {
        const float pv = p[k], qv = q[k], r0v = r0[k];
        const float av = cut_a[k], bv = cut_b[k];
        const float ib = 1.0f / (bv - av);
        pU1[k] = -pv * L2E / r0v;
        pC1[k] =  pv * L2E + __log2f(A[k]);
        pU2[k] = -2.0f * qv * L2E / r0v;
        pC2[k] =  2.0f * qv * L2E + 2.0f * __log2f(xi[k]);
        pIB[k] = ib;
        pNA[k] = -av * ib;
    }

    const int lane = threadIdx.x & 31;
    const int w    = threadIdx.x >> 5;

    const int colBase = tj * TS;                 // atom index of lane-col 0
    const int rowBase = ti * TS + half * HROWS;  // first atom row of this block

    // t_j for this lane's 4 columns: constant for the whole block
    const int4 t4 = *reinterpret_cast<const int4*>(&types[(size_t)b * N + colBase + lane * 4]);
    const bool s0 = t4.x != 0, s1 = t4.y != 0, s2 = t4.z != 0, s3 = t4.w != 0;

    float cphi0 = 0.f, cphi1 = 0.f, cphi2 = 0.f, cphi3 = 0.f;
    float crho0 = 0.f, crho1 = 0.f, crho2 = 0.f, crho3 = 0.f;

    const float* __restrict__ dbase =
        dist + ((size_t)b * N + rowBase) * N + colBase + lane * 4;

#define EAM_E(rv, S, CP, CR, DO_COL)                                          \
    {                                                                         \
        const float u1 = S ? U1b : U1a, c1 = S ? C1b : C1a;                   \
        const float u2 = S ? U2b : U2a, c2 = S ? C2b : C2a;                   \
        const float ib = S ? IBb : IBa, na = S ? NAb : NAa;                   \
        const float x  = fma_sat(rv, ib, na);                                 \
        const float fc = fmaf(x * x, fmaf(2.0f, x, -3.0f), 1.0f);             \
        const float t1 = fc * ex2_approx(fmaf(u1, rv, c1));                   \
        const float t2 = fc * ex2_approx(fmaf(u2, rv, c2));                   \
        sphi += t1; srho += t2;                                               \
        if (DO_COL) { CP += t1; CR += t2; }                                   \
    }

#define EAM_ROW_LOOP(DO_COL)                                                  \
    for (int r = w; r < HROWS; r += 8) {                                      \
        const int gi  = rowBase + r;                                          \
        const int t_i = types[(size_t)b * N + gi];                            \
        const bool ri = (t_i != 0);                                           \
        const float U1a = ri ? pU1[1] : pU1[0], U1b = ri ? pU1[2] : pU1[1];   \
        const float C1a = ri ? pC1[1] : pC1[0], C1b = ri ? pC1[2] : pC1[1];   \
        const float U2a = ri ? pU2[1] : pU2[0], U2b = ri ? pU2[2] : pU2[1];   \
        const float C2a = ri ? pC2[1] : pC2[0], C2b = ri ? pC2[2] : pC2[1];   \
        const float IBa = ri ? pIB[1] : pIB[0], IBb = ri ? pIB[2] : pIB[1];   \
        const float NAa = ri ? pNA[1] : pNA[0], NAb = ri ? pNA[2] : pNA[1];   \
        const float4 r4 = *reinterpret_cast<const float4*>(dbase + (size_t)r * N); \
        float sphi = 0.0f, srho = 0.0f;                                       \
        EAM_E(r4.x, s0, cphi0, crho0, DO_COL)                                 \
        EAM_E(r4.y, s1, cphi1, crho1, DO_COL)                                 \
        EAM_E(r4.z, s2, cphi2, crho2, DO_COL)                                 \
        EAM_E(r4.w, s3, cphi3, crho3, DO_COL)                                 \
        _Pragma("unroll")                                                     \
        for (int o = 16; o > 0; o >>= 1) {                                    \
            sphi += __shfl_down_sync(0xFFFFFFFFu, sphi, o);                   \
            srho += __shfl_down_sync(0xFFFFFFFFu, srho, o);                   \
        }                                                                     \
        if (lane == 0) {                                                      \
            atomicAdd(&g_phi[(size_t)b * N + gi], f2fix(sphi));               \
            atomicAdd(&g_rho[(size_t)b * N + gi], f2fix(srho));               \
        }                                                                     \
    }

    if (diag) { EAM_ROW_LOOP(false) }
    else      { EAM_ROW_LOOP(true)  }

    // ── column (mirror) contributions: combine 8 warps then atomic ──
    __shared__ float2 sc[8][TS];
    if (!diag) {
        sc[w][lane * 4 + 0] = make_float2(cphi0, crho0);
        sc[w][lane * 4 + 1] = make_float2(cphi1, crho1);
        sc[w][lane * 4 + 2] = make_float2(cphi2, crho2);
        sc[w][lane * 4 + 3] = make_float2(cphi3, crho3);
        __syncthreads();
        const int c = threadIdx.x;
        if (c < TS) {
            float ap = 0.f, ar = 0.f;
            #pragma unroll
            for (int k = 0; k < 8; k++) { ap += sc[k][c].x; ar += sc[k][c].y; }
            const size_t gj = (size_t)b * N + colBase + c;
            atomicAdd(&g_phi[gj], f2fix(ap));
            atomicAdd(&g_rho[gj], f2fix(ar));
        }
    }

    // ── last-block-done: fused finalize ──
    __threadfence();
    __shared__ bool is_last;
    if (threadIdx.x == 0)
        is_last = (atomicAdd(&g_ticket, 1u) == gridDim.x - 1u);
    __syncthreads();
    if (!is_last) return;

    __threadfence();
    __shared__ unsigned long long eb[MAX_B];
    __shared__ int cb[MAX_B];
    if (threadIdx.x < MAX_B) { eb[threadIdx.x] = 0ull; cb[threadIdx.x] = 0; }
    __syncthreads();

    // 16 threads per batch (assumes B <= 16 here via fast-path guard B*16<=256;
    // generally: tpb threads per batch)
    const int tpb = 256 / (B > 0 ? B : 1) > 0 ? (256 / B) : 1;
    const int mb  = threadIdx.x / tpb;        // batch handled by this thread
    const int sl  = threadIdx.x % tpb;
    if (mb < B) {
        long long esum = 0; int csum = 0;
        for (int i = sl; i < N; i += tpb) {
            const size_t k = (size_t)mb * N + i;
            const long long ph = (long long)__ldcg(&g_phi[k]);
            const long long rh = (long long)__ldcg(&g_rho[k]);
            g_phi[k] = 0ull; g_rho[k] = 0ull;          // reset for next replay
            const float sp = (float)((double)ph / FIX_SCALE);
            const float sr = (float)((double)rh / FIX_SCALE);
            const int   t  = types[k];
            const float emb = fmaf(-emb_scale[t], sqrtf(fmaxf(sr, 0.0f)), offset[t]);
            const float ae  = fmaf(0.5f, sp, emb);
            esum += (long long)__float2ll_rn(ae * (float)FIX_SCALE);
            if (t >= 0) csum++;
        }
        atomicAdd(&eb[mb], (unsigned long long)esum);
        atomicAdd(&cb[mb], csum);
    }
    __syncthreads();
    if (threadIdx.x < (unsigned)B) {
        const float E = (float)((double)(long long)eb[threadIdx.x] / FIX_SCALE);
        out[2 * threadIdx.x]     = E;
        out[2 * threadIdx.x + 1] = E / (float)cb[threadIdx.x];
    }
    __syncthreads();
    if (threadIdx.x == 0) g_ticket = 0u;
}

// ───────────────────────── fallback path (R2 kernel) ─────────────────────────

__global__ void __launch_bounds__(256)
eam_warp_kernel(const float* __restrict__ dist, const int* __restrict__ types,
                const float* __restrict__ A,  const float* __restrict__ p,
                const float* __restrict__ xi, const float* __restrict__ q,
                const float* __restrict__ r0, const float* __restrict__ cut_a,
                const float* __restrict__ cut_b,
                const float* __restrict__ emb_scale,
                const float* __restrict__ offset, int N, int NT)
{
    const int lane = threadIdx.x & 31;
    const int row  = blockIdx.x * (blockDim.x >> 5) + (threadIdx.x >> 5);
    const int b    = row / N;
    const int t_i  = types[row];
    const float L2E = 1.4426950408889634f;
    float sphi = 0.0f, srho = 0.0f;
    for (int j = lane; j < N; j += 32) {
        const int pt = pair_type(t_i, types[(size_t)b * N + j], NT);
        const float r = dist[(size_t)row * N + j];
        const float ib = 1.0f / (cut_b[pt] - cut_a[pt]);
        const float x = fma_sat(r, ib, -cut_a[pt] * ib);
        const float fc = fmaf(x * x, fmaf(2.0f, x, -3.0f), 1.0f);
        const float rn = r / r0[pt] - 1.0f;
        sphi = fmaf(A[pt] * fc, ex2_approx(-p[pt] * L2E * rn), sphi);
        srho = fmaf(xi[pt] * xi[pt] * fc, ex2_approx(-2.0f * q[pt] * L2E * rn), srho);
    }
    #pragma unroll
    for (int o = 16; o > 0; o >>= 1) {
        sphi += __shfl_down_sync(0xFFFFFFFFu, sphi, o);
        srho += __shfl_down_sync(0xFFFFFFFFu, srho, o);
    }
    if (lane == 0) {
        const float emb = fmaf(-emb_scale[t_i], sqrtf(srho), offset[t_i]);
        const float ae  = fmaf(0.5f, sphi, emb);
        atomicAdd(reinterpret_cast<unsigned long long*>(&g_energy_fix[b]),
                  (unsigned long long)(long long)__float2ll_rn(ae * (float)FIX_SCALE));
        if (t_i >= 0) atomicAdd(&g_count[b], 1);
    }
}

__global__ void eam_finalize_kernel(float* __restrict__ out, int B)
{
    const int i = threadIdx.x;
    if (i < B) {
        const float E = (float)((double)g_energy_fix[i] / FIX_SCALE);
        out[2 * i]     = E;
        out[2 * i + 1] = E / (float)g_count[i];
        g_energy_fix[i] = 0;
        g_count[i]      = 0;
    }
}

// ───────────────────────────── launcher ─────────────────────────────

extern "C" void kernel_launch(void* const* d_in, const int* in_sizes, int n_in,
                              void* d_out, int out_size)
{
    const float* dist      = (const float*)d_in[0];
    const float* A         = (const float*)d_in[1];
    const float* p         = (const float*)d_in[2];
    const float* xi        = (const float*)d_in[3];
    const float* q         = (const float*)d_in[4];
    const float* r0        = (const float*)d_in[5];
    const float* cut_a     = (const float*)d_in[6];
    const float* cut_b     = (const float*)d_in[7];
    const float* emb_scale = (const float*)d_in[8];
    const float* offset    = (const float*)d_in[9];
    const int*   types     = (const int*)d_in[10];
    float* out = (float*)d_out;

    const long long dist_sz  = in_sizes[0];   // B*N*N
    const long long types_sz = in_sizes[10];  // B*N
    const int N   = (int)(dist_sz / types_sz);
    const int B   = (int)(types_sz / N);
    const int NT  = in_sizes[8];
    const int NPT = in_sizes[1];

    const bool fast = (NT == 2) && (NPT >= 3) && (N % TS == 0) &&
                      ((long long)B * N <= MAX_BN) && (B <= 16) && (256 % B == 0);

    if (fast) {
        const int ntile = N / TS;
        const int upb   = ntile * (ntile + 1) / 2;
        const int grid  = B * upb * 2;
        eam_tile_kernel<<<grid, 256>>>(dist, types, A, p, xi, q, r0,
                                       cut_a, cut_b, emb_scale, offset,
                                       N, B, ntile, upb, out);
    } else {
        const int warps_per_block = 8;
        const int nblocks = (B * N + warps_per_block - 1) / warps_per_block;
        eam_warp_kernel<<<nblocks, warps_per_block * 32>>>(
            dist, types, A, p, xi, q, r0, cut_a, cut_b, emb_scale, offset, N, NT);
        eam_finalize_kernel<<<1, 64>>>(out, B);
    }
}

// round 7
// speedup vs baseline: 1.6068x; 1.6068x over previous
#include <cuda_runtime.h>
#include <cuda_bf16.h>
#include <cstdint>

// EAM potential — fused single-kernel warp-per-row (NT==2 fast path).
// Each warp owns one (b,i) row: sum phi/rho over j, write atomic energy to
// g_ae; last block (ticket) reduces per-batch energy deterministically in
// int64 fixed point and writes [B,2] = {E, E/n_atoms}.
//
// Inputs (metadata order):
//   0 distances [B,N,N] f32   1 A[NPT]   2 p[NPT]   3 xi[NPT]   4 q[NPT]
//   5 r0[NPT]  6 cut_a[NPT]   7 cut_b[NPT]  8 emb_scale[NT]  9 offset[NT]
//  10 types [B,N] i32        11 pair_types (UNUSED, recomputed from types)

#define MAX_B   64
#define MAX_BN  65536
#define FIX_SCALE 268435456.0   // 2^28 fixed point (exact, order-independent)

__device__ float        g_ae[MAX_BN];
__device__ unsigned int g_ticket;
// fallback scratch
__device__ long long g_energy_fix[MAX_B];
__device__ int       g_count[MAX_B];

__device__ __forceinline__ float ex2_approx(float x) {
    float y; asm("ex2.approx.f32 %0, %1;" : "=f"(y) : "f"(x)); return y;
}
__device__ __forceinline__ float fma_sat(float a, float b, float c) {
    float y; asm("fma.rn.sat.f32 %0, %1, %2, %3;" : "=f"(y) : "f"(a), "f"(b), "f"(c)); return y;
}
__device__ __forceinline__ int pair_type(int ti, int tj, int NT) {
    int tmin = min(ti, tj), tmax = max(ti, tj);
    return tmin * NT - (tmin * (tmin - 1)) / 2 + (tmax - tmin);
}

struct P2 {
    float U10, U11, C10, C11;   // exp args for phi  (A folded in)
    float U20, U21, C20, C21;   // exp args for rho  (xi^2 folded in)
    float IB0, IB1, NA0, NA1;   // cutoff: x = r*IB + NA, saturated
};

template <bool UNICUT>
__device__ __forceinline__ void eam_elem(float r, bool s, const P2& P,
                                         float& sphi, float& srho)
{
    const float ib = UNICUT ? P.IB0 : (s ? P.IB1 : P.IB0);
    const float na = UNICUT ? P.NA0 : (s ? P.NA1 : P.NA0);
    const float x  = fma_sat(r, ib, na);
    const float fc = fmaf(x * x, fmaf(2.0f, x, -3.0f), 1.0f);
    const float a1 = fmaf(s ? P.U11 : P.U10, r, s ? P.C11 : P.C10);
    const float a2 = fmaf(s ? P.U21 : P.U20, r, s ? P.C21 : P.C20);
    sphi = fmaf(fc, ex2_approx(a1), sphi);
    srho = fmaf(fc, ex2_approx(a2), srho);
}

template <bool UNICUT>
__device__ __forceinline__ void eam_row(const float4* __restrict__ drow,
                                        const int4*   __restrict__ trow,
                                        int nv, int lane, const P2& P,
                                        float& sphi_out, float& srho_out)
{
    float sphiA = 0.f, srhoA = 0.f, sphiB = 0.f, srhoB = 0.f;
    #pragma unroll 4
    for (int v = lane; v < nv; v += 64) {
        const float4 rA = drow[v];
        const int4   tA = trow[v];
        const int vb = v + 32;
        if (vb < nv) {
            const float4 rB = drow[vb];
            const int4   tB = trow[vb];
            eam_elem<UNICUT>(rA.x, tA.x != 0, P, sphiA, srhoA);
            eam_elem<UNICUT>(rA.y, tA.y != 0, P, sphiA, srhoA);
            eam_elem<UNICUT>(rA.z, tA.z != 0, P, sphiA, srhoA);
            eam_elem<UNICUT>(rA.w, tA.w != 0, P, sphiA, srhoA);
            eam_elem<UNICUT>(rB.x, tB.x != 0, P, sphiB, srhoB);
            eam_elem<UNICUT>(rB.y, tB.y != 0, P, sphiB, srhoB);
            eam_elem<UNICUT>(rB.z, tB.z != 0, P, sphiB, srhoB);
            eam_elem<UNICUT>(rB.w, tB.w != 0, P, sphiB, srhoB);
        } else {
            eam_elem<UNICUT>(rA.x, tA.x != 0, P, sphiA, srhoA);
            eam_elem<UNICUT>(rA.y, tA.y != 0, P, sphiA, srhoA);
            eam_elem<UNICUT>(rA.z, tA.z != 0, P, sphiA, srhoA);
            eam_elem<UNICUT>(rA.w, tA.w != 0, P, sphiA, srhoA);
        }
    }
    sphi_out = sphiA + sphiB;
    srho_out = srhoA + srhoB;
}

__global__ void __launch_bounds__(256)
eam_fused_kernel(const float* __restrict__ dist,      // [B,N,N]
                 const int*   __restrict__ types,     // [B,N]
                 const float* __restrict__ A,  const float* __restrict__ p,
                 const float* __restrict__ xi, const float* __restrict__ q,
                 const float* __restrict__ r0, const float* __restrict__ cut_a,
                 const float* __restrict__ cut_b,
                 const float* __restrict__ emb_scale,
                 const float* __restrict__ offset,
                 int N, int B, float* __restrict__ out)
{
    const int lane = threadIdx.x & 31;
    const int row  = blockIdx.x * (blockDim.x >> 5) + (threadIdx.x >> 5);
    const int BN   = B * N;

    if (row < BN) {
        const int b   = row / N;
        const int t_i = types[row];

        // Register-resident per-t_j params (t_i warp-uniform, NT==2).
        const float L2E = 1.4426950408889634f;
        P2 P;
        {
            float U1[2], C1[2], U2[2], C2[2], IB[2], NA[2];
            #pragma unroll
            for (int t = 0; t < 2; t++) {
                const int pt = pair_type(t_i, t, 2);
                const float pv = p[pt], qv = q[pt], r0v = r0[pt];
                const float av = cut_a[pt], bv = cut_b[pt];
                const float ib = 1.0f / (bv - av);
                U1[t] = -pv * L2E / r0v;
                C1[t] =  pv * L2E + __log2f(A[pt]);
                U2[t] = -2.0f * qv * L2E / r0v;
                C2[t] =  2.0f * qv * L2E + 2.0f * __log2f(xi[pt]);
                IB[t] = ib;
                NA[t] = -av * ib;
            }
            P.U10 = U1[0]; P.U11 = U1[1]; P.C10 = C1[0]; P.C11 = C1[1];
            P.U20 = U2[0]; P.U21 = U2[1]; P.C20 = C2[0]; P.C21 = C2[1];
            P.IB0 = IB[0]; P.IB1 = IB[1]; P.NA0 = NA[0]; P.NA1 = NA[1];
        }
        const bool unicut = (P.IB0 == P.IB1) && (P.NA0 == P.NA1);

        const float4* __restrict__ drow =
            reinterpret_cast<const float4*>(dist + (size_t)row * N);
        const int4* __restrict__ trow =
            reinterpret_cast<const int4*>(types + (size_t)b * N);
        const int nv = N >> 2;

        float sphi, srho;
        if (unicut) eam_row<true >(drow, trow, nv, lane, P, sphi, srho);
        else        eam_row<false>(drow, trow, nv, lane, P, sphi, srho);

        #pragma unroll
        for (int o = 16; o > 0; o >>= 1) {
            sphi += __shfl_down_sync(0xFFFFFFFFu, sphi, o);
            srho += __shfl_down_sync(0xFFFFFFFFu, srho, o);
        }
        if (lane == 0) {
            const float emb = fmaf(-emb_scale[t_i], sqrtf(srho), offset[t_i]);
            g_ae[row] = fmaf(0.5f, sphi, emb);
        }
    }

    // ── last-block ticket → fused finalize ──
    __threadfence();
    __shared__ unsigned int rank_s;
    if (threadIdx.x == 0) rank_s = atomicAdd(&g_ticket, 1u);
    __syncthreads();
    if (rank_s != gridDim.x - 1u) return;
    __threadfence();

    __shared__ unsigned long long eb[MAX_B];
    __shared__ int cb[MAX_B];
    if (threadIdx.x < MAX_B) { eb[threadIdx.x] = 0ull; cb[threadIdx.x] = 0; }
    __syncthreads();

    const int tpb = 256 / B;                 // guard: 256 % B == 0
    const int mb  = threadIdx.x / tpb;
    const int sl  = threadIdx.x % tpb;
    if (mb < B) {
        long long esum = 0; int csum = 0;
        for (int i = sl; i < N; i += tpb) {
            const size_t k = (size_t)mb * N + i;
            const float ae = __ldcg(&g_ae[k]);
            esum += (long long)__float2ll_rn(ae * (float)FIX_SCALE);
            if (types[k] >= 0) csum++;
        }
        atomicAdd(&eb[mb], (unsigned long long)esum);
        atomicAdd(&cb[mb], csum);
    }
    __syncthreads();
    if (threadIdx.x < (unsigned)B) {
        const float E = (float)((double)(long long)eb[threadIdx.x] / FIX_SCALE);
        out[2 * threadIdx.x]     = E;
        out[2 * threadIdx.x + 1] = E / (float)cb[threadIdx.x];
    }
    __syncthreads();
    if (threadIdx.x == 0) g_ticket = 0u;     // reset for next graph replay
}

// ───────────────────────── fallback path (generic) ─────────────────────────

__global__ void __launch_bounds__(256)
eam_warp_kernel(const float* __restrict__ dist, const int* __restrict__ types,
                const float* __restrict__ A,  const float* __restrict__ p,
                const float* __restrict__ xi, const float* __restrict__ q,
                const float* __restrict__ r0, const float* __restrict__ cut_a,
                const float* __restrict__ cut_b,
                const float* __restrict__ emb_scale,
                const float* __restrict__ offset, int N, int NT)
{
    const int lane = threadIdx.x & 31;
    const int row  = blockIdx.x * (blockDim.x >> 5) + (threadIdx.x >> 5);
    const int b    = row / N;
    const int t_i  = types[row];
    const float L2E = 1.4426950408889634f;
    float sphi = 0.0f, srho = 0.0f;
    for (int j = lane; j < N; j += 32) {
        const int pt = pair_type(t_i, types[(size_t)b * N + j], NT);
        const float r = dist[(size_t)row * N + j];
        const float ib = 1.0f / (cut_b[pt] - cut_a[pt]);
        const float x = fma_sat(r, ib, -cut_a[pt] * ib);
        const float fc = fmaf(x * x, fmaf(2.0f, x, -3.0f), 1.0f);
        const float rn = r / r0[pt] - 1.0f;
        sphi = fmaf(A[pt] * fc, ex2_approx(-p[pt] * L2E * rn), sphi);
        srho = fmaf(xi[pt] * xi[pt] * fc, ex2_approx(-2.0f * q[pt] * L2E * rn), srho);
    }
    #pragma unroll
    for (int o = 16; o > 0; o >>= 1) {
        sphi += __shfl_down_sync(0xFFFFFFFFu, sphi, o);
        srho += __shfl_down_sync(0xFFFFFFFFu, srho, o);
    }
    if (lane == 0) {
        const float emb = fmaf(-emb_scale[t_i], sqrtf(srho), offset[t_i]);
        const float ae  = fmaf(0.5f, sphi, emb);
        atomicAdd(reinterpret_cast<unsigned long long*>(&g_energy_fix[b]),
                  (unsigned long long)(long long)__float2ll_rn(ae * (float)FIX_SCALE));
        if (t_i >= 0) atomicAdd(&g_count[b], 1);
    }
}

__global__ void eam_finalize_kernel(float* __restrict__ out, int B)
{
    const int i = threadIdx.x;
    if (i < B) {
        const float E = (float)((double)g_energy_fix[i] / FIX_SCALE);
        out[2 * i]     = E;
        out[2 * i + 1] = E / (float)g_count[i];
        g_energy_fix[i] = 0;
        g_count[i]      = 0;
    }
}

// ───────────────────────────── launcher ─────────────────────────────

extern "C" void kernel_launch(void* const* d_in, const int* in_sizes, int n_in,
                              void* d_out, int out_size)
{
    const float* dist      = (const float*)d_in[0];
    const float* A         = (const float*)d_in[1];
    const float* p         = (const float*)d_in[2];
    const float* xi        = (const float*)d_in[3];
    const float* q         = (const float*)d_in[4];
    const float* r0        = (const float*)d_in[5];
    const float* cut_a     = (const float*)d_in[6];
    const float* cut_b     = (const float*)d_in[7];
    const float* emb_scale = (const float*)d_in[8];
    const float* offset    = (const float*)d_in[9];
    const int*   types     = (const int*)d_in[10];
    float* out = (float*)d_out;

    const long long dist_sz  = in_sizes[0];   // B*N*N
    const long long types_sz = in_sizes[10];  // B*N
    const int N   = (int)(dist_sz / types_sz);
    const int B   = (int)(types_sz / N);
    const int NT  = in_sizes[8];
    const int NPT = in_sizes[1];

    const bool fast = (NT == 2) && (NPT >= 3) && ((N & 3) == 0) &&
                      ((long long)B * N <= MAX_BN) && (B >= 1) && (B <= MAX_B) &&
                      (256 % B == 0) && ((B * N) % 8 == 0);

    if (fast) {
        const int warps_per_block = 8;
        const int nblocks = (B * N) / warps_per_block;
        eam_fused_kernel<<<nblocks, warps_per_block * 32>>>(
            dist, types, A, p, xi, q, r0, cut_a, cut_b, emb_scale, offset,
            N, B, out);
    } else {
        const int warps_per_block = 8;
        const int nblocks = (B * N + warps_per_block - 1) / warps_per_block;
        eam_warp_kernel<<<nblocks, warps_per_block * 32>>>(
            dist, types, A, p, xi, q, r0, cut_a, cut_b, emb_scale, offset, N, NT);
        eam_finalize_kernel<<<1, 64>>>(out, B);
    }
}

// round 9
// speedup vs baseline: 2.1624x; 1.3457x over previous
#include <cuda_runtime.h>
#include <cuda_bf16.h>
#include <cstdint>

// EAM potential — single fused kernel, warp-per-row, compile-time row length.
// Lane-0 per warp accumulates row energy into per-batch int64 fixed-point
// atomics (exact, order-independent => deterministic); last block (ticket)
// writes [B,2] = {E, E/n_atoms} and resets scratch for graph replay.
//
// Inputs (metadata order):
//   0 distances [B,N,N] f32   1 A[NPT]   2 p[NPT]   3 xi[NPT]   4 q[NPT]
//   5 r0[NPT]  6 cut_a[NPT]   7 cut_b[NPT]  8 emb_scale[NT]  9 offset[NT]
//  10 types [B,N] i32        11 pair_types (UNUSED, recomputed from types)

#define MAX_B   64
#define FIX_SCALE 268435456.0   // 2^28

__device__ long long     g_energy_fix[MAX_B];   // zero-init; reset each run
__device__ int           g_count[MAX_B];
__device__ unsigned int  g_ticket;

__device__ __forceinline__ float ex2_approx(float x) {
    float y; asm("ex2.approx.f32 %0, %1;" : "=f"(y) : "f"(x)); return y;
}
__device__ __forceinline__ float fma_sat(float a, float b, float c) {
    float y; asm("fma.rn.sat.f32 %0, %1, %2, %3;" : "=f"(y) : "f"(a), "f"(b), "f"(c)); return y;
}
__device__ __forceinline__ int pair_type(int ti, int tj, int NT) {
    int tmin = min(ti, tj), tmax = max(ti, tj);
    return tmin * NT - (tmin * (tmin - 1)) / 2 + (tmax - tmin);
}

// ───────────────────────── fast path (NT == 2) ─────────────────────────
// NV = N/4 (float4 groups per row). NV > 0: compile-time; identical loop body
// to the proven R2 kernel, fully unrolled, single code path.

template <int NV>
__global__ void __launch_bounds__(256)
eam_fused_kernel(const float* __restrict__ dist,      // [B,N,N]
                 const int*   __restrict__ types,     // [B,N]
                 const float* __restrict__ A,  const float* __restrict__ p,
                 const float* __restrict__ xi, const float* __restrict__ q,
                 const float* __restrict__ r0, const float* __restrict__ cut_a,
                 const float* __restrict__ cut_b,
                 const float* __restrict__ emb_scale,
                 const float* __restrict__ offset,
                 int N, int B, float* __restrict__ out)
{
    const int lane = threadIdx.x & 31;
    const int row  = blockIdx.x * 8 + (threadIdx.x >> 5);
    const int b    = row / N;
    const int t_i  = types[row];

    // register-resident params for t_j = 0 / 1 (NT==2 -> pt = t_i + t_j)
    const float L2E = 1.4426950408889634f;
    float U1[2], C1[2], U2[2], C2[2], IB[2], NA[2];
    #pragma unroll
    for (int t = 0; t < 2; t++) {
        const int pt = t_i + t;
        const float pv = p[pt], qv = q[pt], r0v = r0[pt];
        const float av = cut_a[pt], bv = cut_b[pt];
        const float ib = 1.0f / (bv - av);
        U1[t] = -pv * L2E / r0v;
        C1[t] =  pv * L2E + __log2f(A[pt]);
        U2[t] = -2.0f * qv * L2E / r0v;
        C2[t] =  2.0f * qv * L2E + 2.0f * __log2f(xi[pt]);
        IB[t] = ib;
        NA[t] = -av * ib;
    }
    const float U10 = U1[0], U11 = U1[1], C10 = C1[0], C11 = C1[1];
    const float U20 = U2[0], U21 = U2[1], C20 = C2[0], C21 = C2[1];
    const float IB0 = IB[0], IB1 = IB[1], NA0 = NA[0], NA1 = NA[1];

    const float4* __restrict__ drow =
        reinterpret_cast<const float4*>(dist + (size_t)row * N);
    const int4* __restrict__ trow =
        reinterpret_cast<const int4*>(types + (size_t)b * N);

    float sphiA = 0.f, srhoA = 0.f, sphiB = 0.f, srhoB = 0.f;

#define EAM_E(rv, tv, SP, SR)                                                  \
    {                                                                          \
        const bool  s  = (tv) != 0;                                            \
        const float r  = (rv);                                                 \
        const float x  = fma_sat(r, s ? IB1 : IB0, s ? NA1 : NA0);             \
        const float fc = fmaf(x * x, fmaf(2.0f, x, -3.0f), 1.0f);              \
        SP = fmaf(fc, ex2_approx(fmaf(s ? U11 : U10, r, s ? C11 : C10)), SP);  \
        SR = fmaf(fc, ex2_approx(fmaf(s ? U21 : U20, r, s ? C21 : C20)), SR);  \
    }

    #pragma unroll
    for (int k = 0; k < NV / 32; k++) {
        const int v = lane + k * 32;
        const float4 r4 = drow[v];
        const int4   t4 = trow[v];
        if (k & 1) {
            EAM_E(r4.x, t4.x, sphiB, srhoB)
            EAM_E(r4.y, t4.y, sphiB, srhoB)
            EAM_E(r4.z, t4.z, sphiB, srhoB)
            EAM_E(r4.w, t4.w, sphiB, srhoB)
        } else {
            EAM_E(r4.x, t4.x, sphiA, srhoA)
            EAM_E(r4.y, t4.y, sphiA, srhoA)
            EAM_E(r4.z, t4.z, sphiA, srhoA)
            EAM_E(r4.w, t4.w, sphiA, srhoA)
        }
    }
#undef EAM_E

    float sphi = sphiA + sphiB;
    float srho = srhoA + srhoB;
    #pragma unroll
    for (int o = 16; o > 0; o >>= 1) {
        sphi += __shfl_down_sync(0xFFFFFFFFu, sphi, o);
        srho += __shfl_down_sync(0xFFFFFFFFu, srho, o);
    }
    if (lane == 0) {
        const float emb = fmaf(-emb_scale[t_i], sqrtf(srho), offset[t_i]);
        const float ae  = fmaf(0.5f, sphi, emb);
        atomicAdd(reinterpret_cast<unsigned long long*>(&g_energy_fix[b]),
                  (unsigned long long)(long long)__float2ll_rn(ae * (float)FIX_SCALE));
        if (t_i >= 0) atomicAdd(&g_count[b], 1);
    }

    // ── last-block ticket → tiny finalize (reads only B accumulators) ──
    __syncthreads();
    __shared__ unsigned int rank_s;
    if (threadIdx.x == 0) {
        __threadfence();
        rank_s = atomicAdd(&g_ticket, 1u);
    }
    __syncthreads();
    if (rank_s != gridDim.x - 1u) return;

    if (threadIdx.x == 0) __threadfence();
    __syncthreads();
    if (threadIdx.x < (unsigned)B) {
        const int i = threadIdx.x;
        const float E = (float)((double)g_energy_fix[i] / FIX_SCALE);
        out[2 * i]     = E;
        out[2 * i + 1] = E / (float)g_count[i];
        g_energy_fix[i] = 0;               // reset for next graph replay
        g_count[i]      = 0;
    }
    __syncthreads();
    if (threadIdx.x == 0) g_ticket = 0u;
}

// ───────────────────────── generic fallback ─────────────────────────

__global__ void __launch_bounds__(256)
eam_warp_kernel(const float* __restrict__ dist, const int* __restrict__ types,
                const float* __restrict__ A,  const float* __restrict__ p,
                const float* __restrict__ xi, const float* __restrict__ q,
                const float* __restrict__ r0, const float* __restrict__ cut_a,
                const float* __restrict__ cut_b,
                const float* __restrict__ emb_scale,
                const float* __restrict__ offset, int N, int NT, int BN)
{
    const int lane = threadIdx.x & 31;
    const int row  = blockIdx.x * (blockDim.x >> 5) + (threadIdx.x >> 5);
    if (row >= BN) return;
    const int b    = row / N;
    const int t_i  = types[row];
    const float L2E = 1.4426950408889634f;
    float sphi = 0.0f, srho = 0.0f;
    for (int j = lane; j < N; j += 32) {
        const int pt = pair_type(t_i, types[(size_t)b * N + j], NT);
        const float r = dist[(size_t)row * N + j];
        const float ib = 1.0f / (cut_b[pt] - cut_a[pt]);
        const float x = fma_sat(r, ib, -cut_a[pt] * ib);
        const float fc = fmaf(x * x, fmaf(2.0f, x, -3.0f), 1.0f);
        const float rn = r / r0[pt] - 1.0f;
        sphi = fmaf(A[pt] * fc, ex2_approx(-p[pt] * L2E * rn), sphi);
        srho = fmaf(xi[pt] * xi[pt] * fc, ex2_approx(-2.0f * q[pt] * L2E * rn), srho);
    }
    #pragma unroll
    for (int o = 16; o > 0; o >>= 1) {
        sphi += __shfl_down_sync(0xFFFFFFFFu, sphi, o);
        srho += __shfl_down_sync(0xFFFFFFFFu, srho, o);
    }
    if (lane == 0) {
        const float emb = fmaf(-emb_scale[t_i], sqrtf(srho), offset[t_i]);
        const float ae  = fmaf(0.5f, sphi, emb);
        atomicAdd(reinterpret_cast<unsigned long long*>(&g_energy_fix[b]),
                  (unsigned long long)(long long)__float2ll_rn(ae * (float)FIX_SCALE));
        if (t_i >= 0) atomicAdd(&g_count[b], 1);
    }
}

__global__ void eam_finalize_kernel(float* __restrict__ out, int B)
{
    const int i = threadIdx.x;
    if (i < B) {
        const float E = (float)((double)g_energy_fix[i] / FIX_SCALE);
        out[2 * i]     = E;
        out[2 * i + 1] = E / (float)g_count[i];
        g_energy_fix[i] = 0;
        g_count[i]      = 0;
    }
}

// ───────────────────────────── launcher ─────────────────────────────

extern "C" void kernel_launch(void* const* d_in, const int* in_sizes, int n_in,
                              void* d_out, int out_size)
{
    const float* dist      = (const float*)d_in[0];
    const float* A         = (const float*)d_in[1];
    const float* p         = (const float*)d_in[2];
    const float* xi        = (const float*)d_in[3];
    const float* q         = (const float*)d_in[4];
    const float* r0        = (const float*)d_in[5];
    const float* cut_a     = (const float*)d_in[6];
    const float* cut_b     = (const float*)d_in[7];
    const float* emb_scale = (const float*)d_in[8];
    const float* offset    = (const float*)d_in[9];
    const int*   types     = (const int*)d_in[10];
    float* out = (float*)d_out;

    const long long dist_sz  = in_sizes[0];   // B*N*N
    const long long types_sz = in_sizes[10];  // B*N
    const int N   = (int)(dist_sz / types_sz);
    const int B   = (int)(types_sz / N);
    const int NT  = in_sizes[8];
    const int NPT = in_sizes[1];
    const int BN  = B * N;

    const bool fast = (NT == 2) && (NPT >= 3) && (B >= 1) && (B <= MAX_B) &&
                      (BN % 8 == 0) &&
                      (N == 1024 || N == 512 || N == 2048);

    if (fast) {
        const int nblocks = BN / 8;
        switch (N) {
        case 512:
            eam_fused_kernel<128><<<nblocks, 256>>>(dist, types, A, p, xi, q, r0,
                cut_a, cut_b, emb_scale, offset, N, B, out); break;
        case 1024:
            eam_fused_kernel<256><<<nblocks, 256>>>(dist, types, A, p, xi, q, r0,
                cut_a, cut_b, emb_scale, offset, N, B, out); break;
        default:
            eam_fused_kernel<512><<<nblocks, 256>>>(dist, types, A, p, xi, q, r0,
                cut_a, cut_b, emb_scale, offset, N, B, out); break;
        }
    } else {
        const int warps_per_block = 8;
        const int nblocks = (BN + warps_per_block - 1) / warps_per_block;
        eam_warp_kernel<<<nblocks, warps_per_block * 32>>>(
            dist, types, A, p, xi, q, r0, cut_a, cut_b, emb_scale, offset,
            N, NT, BN);
        eam_finalize_kernel<<<1, 64>>>(out, B);
    }
}

// round 13
// speedup vs baseline: 2.2066x; 1.0205x over previous
#include <cuda_runtime.h>
#include <cuda_bf16.h>
#include <cstdint>

// EAM potential — single fused kernel, warp-per-row, compile-time row length,
// 32-byte L2-persistent distance loads, high-occupancy launch bounds.
// Lane-0 per warp accumulates row energy into per-batch int64 fixed-point
// atomics (exact, order-independent => deterministic); last block (ticket)
// writes [B,2] = {E, E/n_atoms} and resets scratch for graph replay.
//
// Inputs (metadata order):
//   0 distances [B,N,N] f32   1 A[NPT]   2 p[NPT]   3 xi[NPT]   4 q[NPT]
//   5 r0[NPT]  6 cut_a[NPT]   7 cut_b[NPT]  8 emb_scale[NT]  9 offset[NT]
//  10 types [B,N] i32        11 pair_types (UNUSED, recomputed from types)

#define MAX_B   64
#define FIX_SCALE 268435456.0   // 2^28

__device__ long long     g_energy_fix[MAX_B];   // zero-init; reset each run
__device__ int           g_count[MAX_B];
__device__ unsigned int  g_ticket;

__device__ __forceinline__ float ex2_approx(float x) {
    float y; asm("ex2.approx.f32 %0, %1;" : "=f"(y) : "f"(x)); return y;
}
__device__ __forceinline__ float fma_sat(float a, float b, float c) {
    float y; asm("fma.rn.sat.f32 %0, %1, %2, %3;" : "=f"(y) : "f"(a), "f"(b), "f"(c)); return y;
}
__device__ __forceinline__ int pair_type(int ti, int tj, int NT) {
    int tmin = min(ti, tj), tmax = max(ti, tj);
    return tmin * NT - (tmin * (tmin - 1)) / 2 + (tmax - tmin);
}

// 32-byte load (8 floats) — .v4.b64 is the form ptxas accepts with
// L2::evict_last on sm_103a. Unpack of u64 halves is free (reg aliasing).
struct F8 { float f[8]; };

template <bool EVL>
__device__ __forceinline__ F8 ldg_f8(const float* ptr) {
    unsigned long long d0, d1, d2, d3;
    if (EVL)
        asm("ld.global.nc.L2::evict_last.v4.b64 {%0,%1,%2,%3}, [%4];"
            : "=l"(d0), "=l"(d1), "=l"(d2), "=l"(d3) : "l"(ptr));
    else
        asm("ld.global.nc.v4.b64 {%0,%1,%2,%3}, [%4];"
            : "=l"(d0), "=l"(d1), "=l"(d2), "=l"(d3) : "l"(ptr));
    F8 r;
    r.f[0] = __uint_as_float((unsigned)d0); r.f[1] = __uint_as_float((unsigned)(d0 >> 32));
    r.f[2] = __uint_as_float((unsigned)d1); r.f[3] = __uint_as_float((unsigned)(d1 >> 32));
    r.f[4] = __uint_as_float((unsigned)d2); r.f[5] = __uint_as_float((unsigned)(d2 >> 32));
    r.f[6] = __uint_as_float((unsigned)d3); r.f[7] = __uint_as_float((unsigned)(d3 >> 32));
    return r;
}

// ───────────────────────── fast path (NT == 2) ─────────────────────────
// NV8 = N/8 32-byte groups per row; each warp does NV8/32 fully-unrolled
// iterations, loads front-batched.

template <int NV8, bool EVL>
__global__ void __launch_bounds__(256, 6)
eam_fused_kernel(const float* __restrict__ dist,      // [B,N,N]
                 const int*   __restrict__ types,     // [B,N]
                 const float* __restrict__ A,  const float* __restrict__ p,
                 const float* __restrict__ xi, const float* __restrict__ q,
                 const float* __restrict__ r0, const float* __restrict__ cut_a,
                 const float* __restrict__ cut_b,
                 const float* __restrict__ emb_scale,
                 const float* __restrict__ offset,
                 int N, int B, float* __restrict__ out)
{
    const int lane = threadIdx.x & 31;
    const int row  = blockIdx.x * 8 + (threadIdx.x >> 5);
    const int b    = row / N;
    const int t_i  = types[row];

    const float* __restrict__ drow = dist + (size_t)row * N;
    const int4*  __restrict__ trow = reinterpret_cast<const int4*>(types + (size_t)b * N);

    // register-resident params for t_j = 0 / 1 (NT==2 -> pt = t_i + t_j)
    const float L2E = 1.4426950408889634f;
    float U1[2], C1[2], U2[2], C2[2], IB[2], NA[2];
    #pragma unroll
    for (int t = 0; t < 2; t++) {
        const int pt = t_i + t;
        const float pv = p[pt], qv = q[pt], r0v = r0[pt];
        const float av = cut_a[pt], bv = cut_b[pt];
        const float ib = 1.0f / (bv - av);
        U1[t] = -pv * L2E / r0v;
        C1[t] =  pv * L2E + __log2f(A[pt]);
        U2[t] = -2.0f * qv * L2E / r0v;
        C2[t] =  2.0f * qv * L2E + 2.0f * __log2f(xi[pt]);
        IB[t] = ib;
        NA[t] = -av * ib;
    }
    const float U10 = U1[0], U11 = U1[1], C10 = C1[0], C11 = C1[1];
    const float U20 = U2[0], U21 = U2[1], C20 = C2[0], C21 = C2[1];
    const float IB0 = IB[0], IB1 = IB[1], NA0 = NA[0], NA1 = NA[1];

    float sphiA = 0.f, srhoA = 0.f, sphiB = 0.f, srhoB = 0.f;

#define EAM_E(rv, tv, SP, SR)                                                  \
    {                                                                          \
        const bool  s  = (tv) != 0;                                            \
        const float r  = (rv);                                                 \
        const float x  = fma_sat(r, s ? IB1 : IB0, s ? NA1 : NA0);             \
        const float fc = fmaf(x * x, fmaf(2.0f, x, -3.0f), 1.0f);              \
        SP = fmaf(fc, ex2_approx(fmaf(s ? U11 : U10, r, s ? C11 : C10)), SP);  \
        SR = fmaf(fc, ex2_approx(fmaf(s ? U21 : U20, r, s ? C21 : C20)), SR);  \
    }

    constexpr int KITER = NV8 / 32;   // iterations per warp (N=1024 -> 4)
    #pragma unroll
    for (int k = 0; k < KITER; k++) {
        const int v8 = lane + k * 32;              // 32-byte group index
        const F8   r8 = ldg_f8<EVL>(drow + v8 * 8);
        const int4 tA = trow[2 * v8];
        const int4 tB = trow[2 * v8 + 1];
        EAM_E(r8.f[0], tA.x, sphiA, srhoA)
        EAM_E(r8.f[1], tA.y, sphiA, srhoA)
        EAM_E(r8.f[2], tA.z, sphiA, srhoA)
        EAM_E(r8.f[3], tA.w, sphiA, srhoA)
        EAM_E(r8.f[4], tB.x, sphiB, srhoB)
        EAM_E(r8.f[5], tB.y, sphiB, srhoB)
        EAM_E(r8.f[6], tB.z, sphiB, srhoB)
        EAM_E(r8.f[7], tB.w, sphiB, srhoB)
    }
#undef EAM_E

    float sphi = sphiA + sphiB;
    float srho = srhoA + srhoB;
    #pragma unroll
    for (int o = 16; o > 0; o >>= 1) {
        sphi += __shfl_down_sync(0xFFFFFFFFu, sphi, o);
        srho += __shfl_down_sync(0xFFFFFFFFu, srho, o);
    }
    if (lane == 0) {
        const float emb = fmaf(-emb_scale[t_i], sqrtf(srho), offset[t_i]);
        const float ae  = fmaf(0.5f, sphi, emb);
        atomicAdd(reinterpret_cast<unsigned long long*>(&g_energy_fix[b]),
                  (unsigned long long)(long long)__float2ll_rn(ae * (float)FIX_SCALE));
        if (t_i >= 0) atomicAdd(&g_count[b], 1);
    }

    // ── last-block ticket → tiny finalize (reads only B accumulators) ──
    __syncthreads();
    __shared__ unsigned int rank_s;
    if (threadIdx.x == 0) {
        __threadfence();
        rank_s = atomicAdd(&g_ticket, 1u);
    }
    __syncthreads();
    if (rank_s != gridDim.x - 1u) return;

    if (threadIdx.x == 0) __threadfence();
    __syncthreads();
    if (threadIdx.x < (unsigned)B) {
        const int i = threadIdx.x;
        const float E = (float)((double)g_energy_fix[i] / FIX_SCALE);
        out[2 * i]     = E;
        out[2 * i + 1] = E / (float)g_count[i];
        g_energy_fix[i] = 0;               // reset for next graph replay
        g_count[i]      = 0;
    }
    __syncthreads();
    if (threadIdx.x == 0) g_ticket = 0u;
}

// ───────────────────────── generic fallback ─────────────────────────

__global__ void __launch_bounds__(256)
eam_warp_kernel(const float* __restrict__ dist, const int* __restrict__ types,
                const float* __restrict__ A,  const float* __restrict__ p,
                const float* __restrict__ xi, const float* __restrict__ q,
                const float* __restrict__ r0, const float* __restrict__ cut_a,
                const float* __restrict__ cut_b,
                const float* __restrict__ emb_scale,
                const float* __restrict__ offset, int N, int NT, int BN)
{
    const int lane = threadIdx.x & 31;
    const int row  = blockIdx.x * (blockDim.x >> 5) + (threadIdx.x >> 5);
    if (row >= BN) return;
    const int b    = row / N;
    const int t_i  = types[row];
    const float L2E = 1.4426950408889634f;
    float sphi = 0.0f, srho = 0.0f;
    for (int j = lane; j < N; j += 32) {
        const int pt = pair_type(t_i, types[(size_t)b * N + j], NT);
        const float r = dist[(size_t)row * N + j];
        const float ib = 1.0f / (cut_b[pt] - cut_a[pt]);
        const float x = fma_sat(r, ib, -cut_a[pt] * ib);
        const float fc = fmaf(x * x, fmaf(2.0f, x, -3.0f), 1.0f);
        const float rn = r / r0[pt] - 1.0f;
        sphi = fmaf(A[pt] * fc, ex2_approx(-p[pt] * L2E * rn), sphi);
        srho = fmaf(xi[pt] * xi[pt] * fc, ex2_approx(-2.0f * q[pt] * L2E * rn), srho);
    }
    #pragma unroll
    for (int o = 16; o > 0; o >>= 1) {
        sphi += __shfl_down_sync(0xFFFFFFFFu, sphi, o);
        srho += __shfl_down_sync(0xFFFFFFFFu, srho, o);
    }
    if (lane == 0) {
        const float emb = fmaf(-emb_scale[t_i], sqrtf(srho), offset[t_i]);
        const float ae  = fmaf(0.5f, sphi, emb);
        atomicAdd(reinterpret_cast<unsigned long long*>(&g_energy_fix[b]),
                  (unsigned long long)(long long)__float2ll_rn(ae * (float)FIX_SCALE));
        if (t_i >= 0) atomicAdd(&g_count[b], 1);
    }
}

__global__ void eam_finalize_kernel(float* __restrict__ out, int B)
{
    const int i = threadIdx.x;
    if (i < B) {
        const float E = (float)((double)g_energy_fix[i] / FIX_SCALE);
        out[2 * i]     = E;
        out[2 * i + 1] = E / (float)g_count[i];
        g_energy_fix[i] = 0;
        g_count[i]      = 0;
    }
}

// ───────────────────────────── launcher ─────────────────────────────

extern "C" void kernel_launch(void* const* d_in, const int* in_sizes, int n_in,
                              void* d_out, int out_size)
{
    const float* dist      = (const float*)d_in[0];
    const float* A         = (const float*)d_in[1];
    const float* p         = (const float*)d_in[2];
    const float* xi        = (const float*)d_in[3];
    const float* q         = (const float*)d_in[4];
    const float* r0        = (const float*)d_in[5];
    const float* cut_a     = (const float*)d_in[6];
    const float* cut_b     = (const float*)d_in[7];
    const float* emb_scale = (const float*)d_in[8];
    const float* offset    = (const float*)d_in[9];
    const int*   types     = (const int*)d_in[10];
    float* out = (float*)d_out;

    const long long dist_sz  = in_sizes[0];   // B*N*N
    const long long types_sz = in_sizes[10];  // B*N
    const int N   = (int)(dist_sz / types_sz);
    const int B   = (int)(types_sz / N);
    const int NT  = in_sizes[8];
    const int NPT = in_sizes[1];
    const int BN  = B * N;

    const bool aligned32 = ((uintptr_t)dist & 31u) == 0;
    const bool fast = (NT == 2) && (NPT >= 3) && (B >= 1) && (B <= MAX_B) &&
                      (BN % 8 == 0) && aligned32 &&
                      (N == 1024 || N == 512 || N == 2048);
    // distances fit comfortably in the 126MB L2? -> keep resident across replays
    const bool evl = (dist_sz * 4ll) <= (96ll << 20);

    if (fast) {
        const int nblocks = BN / 8;
        #define LAUNCH(NV8V)                                                       \
            if (evl) eam_fused_kernel<NV8V, true ><<<nblocks, 256>>>(dist, types,  \
                A, p, xi, q, r0, cut_a, cut_b, emb_scale, offset, N, B, out);      \
            else     eam_fused_kernel<NV8V, false><<<nblocks, 256>>>(dist, types,  \
                A, p, xi, q, r0, cut_a, cut_b, emb_scale, offset, N, B, out);
        switch (N) {
        case 512:  LAUNCH(64)  break;
        case 1024: LAUNCH(128) break;
        default:   LAUNCH(256) break;
        }
        #undef LAUNCH
    } else {
        const int warps_per_block = 8;
        const int nblocks = (BN + warps_per_block - 1) / warps_per_block;
        eam_warp_kernel<<<nblocks, warps_per_block * 32>>>(
            dist, types, A, p, xi, q, r0, cut_a, cut_b, emb_scale, offset,
            N, NT, BN);
        eam_finalize_kernel<<<1, 64>>>(out, B);
    }
}